// round 1
// baseline (speedup 1.0000x reference)
#include <cuda_runtime.h>
#include <cstdint>

// ---------------------------------------------------------------------------
// SRNN forward. Reference semantics:
//   inp_cur[t,b,r] = sum_i x[b,i,t] * w_inp[r,i]
//   per step t=0..997 (999 steps total, n_t-1):
//     v1  = ALPHA*v + z @ w_rec_eff.T + inp_cur[t] - z*THR    (w_rec diag zeroed)
//     z1  = (v1 > THR)
//     vo1 = KAPPA*vo + z1 @ w_out.T
//   out[0] = 0, out[t+1] = vo1 at step t.   out shape (1000,128,32) f32
// ---------------------------------------------------------------------------

#define N_B      128
#define INP_DIM  256
#define N_T      1000
#define N_REC    512
#define OUT_DIM  32
#define N_STEPS  999          // steps of work (uses inp_cur[0..998])

#define ALPHA 0.9512294245007140f   // exp(-0.001/0.02)
#define KAPPA 0.9512294245007140f
#define THR   0.6f

#define ROWS  (N_STEPS * N_B)       // 127872 = 864 * 148 exactly
#define ROWS_PER_CTA 864

// ---- scratch (allocation-free: __device__ globals) ----
__device__ float    g_inp[(size_t)ROWS * N_REC];        // (t,b,r) input currents, 262 MB
__device__ unsigned g_masks[(size_t)ROWS * 8];          // 256-bit spike mask per (t,b)
__device__ float    g_wrecT[N_REC * N_REC];             // w_recT[s][r] = w_rec[r][s], diag 0
__device__ float    g_woutT[N_REC * OUT_DIM];           // w_outT[r][o] = w_out[o][r]
__device__ float    g_winpT[INP_DIM * N_REC];           // w_inpT[i][r] = w_inp[r][i]

// ---------------------------------------------------------------------------
// Kernel 1: pack x (b, i, t) into per-(t,b) bitmasks. Coalesced over t.
// ---------------------------------------------------------------------------
__global__ void k_masks(const float* __restrict__ x) {
    int b = blockIdx.x;
    int t = blockIdx.y * 256 + threadIdx.x;
    if (t >= N_STEPS) return;

    unsigned m[8] = {0, 0, 0, 0, 0, 0, 0, 0};
    const float* xp = x + (size_t)b * INP_DIM * N_T + t;
#pragma unroll
    for (int i = 0; i < INP_DIM; i++) {
        if (xp[(size_t)i * N_T] > 0.5f) m[i >> 5] |= (1u << (i & 31));
    }
    unsigned* dst = g_masks + ((size_t)t * N_B + b) * 8;
#pragma unroll
    for (int w = 0; w < 8; w++) dst[w] = m[w];
}

// ---------------------------------------------------------------------------
// Kernel 2: weight transposes (coalesced gather layouts for the scan / GEMM).
// ---------------------------------------------------------------------------
__global__ void k_prep(const float* __restrict__ w_rec,
                       const float* __restrict__ w_out,
                       const float* __restrict__ w_inp) {
    int stride = gridDim.x * blockDim.x;
    int idx0 = blockIdx.x * blockDim.x + threadIdx.x;

    for (int i = idx0; i < N_REC * N_REC; i += stride) {
        int s = i >> 9, r = i & (N_REC - 1);
        float v = w_rec[(size_t)r * N_REC + s];
        g_wrecT[i] = (r == s) ? 0.0f : v;
    }
    for (int i = idx0; i < N_REC * OUT_DIM; i += stride) {
        int r = i >> 5, o = i & 31;
        g_woutT[i] = w_out[(size_t)o * N_REC + r];
    }
    for (int i = idx0; i < INP_DIM * N_REC; i += stride) {
        int ii = i >> 9, r = i & (N_REC - 1);
        g_winpT[i] = w_inp[(size_t)r * INP_DIM + ii];
    }
}

// ---------------------------------------------------------------------------
// Kernel 3: sparse input GEMM.
//   grid (4 rec-slices, 148 chunks), 256 threads.
//   Shared: w_inpT slice [256 i][128 r] fp32 (128 KB) + partial buffer.
//   Thread layout: half = tid>>7 owns 4 mask words, rl = tid&127 owns one r.
// ---------------------------------------------------------------------------
#define K_INP_SMEM ((INP_DIM * 128 + 256) * 4)

__global__ void __launch_bounds__(256) k_inp_kernel() {
    extern __shared__ float sm[];
    float* w_sh = sm;                       // [256][128]
    float* part = sm + INP_DIM * 128;       // [2][128]

    int slice = blockIdx.x;                 // 0..3
    int chunk = blockIdx.y;                 // 0..147
    int tid   = threadIdx.x;
    int rl    = tid & 127;
    int half  = tid >> 7;
    int r0    = slice * 128;

    // stage weight slice: consecutive threads -> consecutive r (coalesced)
    for (int idx = tid; idx < INP_DIM * 128; idx += 256) {
        int i = idx >> 7, rr = idx & 127;
        w_sh[idx] = g_winpT[(size_t)i * N_REC + r0 + rr];
    }
    __syncthreads();

    int rowbase = chunk * ROWS_PER_CTA;
    for (int j = 0; j < ROWS_PER_CTA; j++) {
        int row = rowbase + j;
        const unsigned* mp = g_masks + (size_t)row * 8 + half * 4;
        float acc = 0.0f;
#pragma unroll
        for (int w = 0; w < 4; w++) {
            unsigned m = mp[w];
            int ibase = (half * 4 + w) * 32;
            while (m) {
                int i = ibase + __ffs((int)m) - 1;
                m &= (m - 1);
                acc += w_sh[(i << 7) + rl];
            }
        }
        int buf = (j & 1) << 7;
        if (half) part[buf + rl] = acc;
        __syncthreads();
        if (!half)
            g_inp[(size_t)row * N_REC + r0 + rl] = acc + part[buf + rl];
        // double-buffered `part` + the one sync per row keeps rows hazard-free
    }
}

// ---------------------------------------------------------------------------
// Kernel 4: sequential scan. 1 CTA per batch, 1 thread per rec neuron.
//   Spikes exchanged via ballot + __syncthreads_or (doubles as "any" flag).
//   Warp 0 owns the 32 outputs. 4-deep register prefetch of g_inp stream.
// ---------------------------------------------------------------------------
__global__ void __launch_bounds__(512) k_scan(float* __restrict__ out) {
    __shared__ unsigned smask[2][16];

    int b    = blockIdx.x;
    int tid  = threadIdx.x;
    int wid  = tid >> 5;
    int lane = tid & 31;

    float v = 0.0f, zf = 0.0f, vo = 0.0f;
    int any_prev = 0, p = 0;

    const float* inp = g_inp + (size_t)b * N_REC + tid;   // + t*N_B*N_REC per step
    const size_t TSTRIDE = (size_t)N_B * N_REC;

    if (wid == 0) out[(size_t)b * OUT_DIM + lane] = 0.0f;  // out[0] = 0

    auto ld = [&](int t) {
        int tc = t < (N_STEPS - 1) ? t : (N_STEPS - 1);    // clamp for tail prefetch
        return inp[(size_t)tc * TSTRIDE];
    };

    float a0 = ld(0), a1 = ld(1), a2 = ld(2), a3 = ld(3);

    for (int t0 = 0; t0 < N_STEPS; t0 += 4) {
        float n0 = ld(t0 + 4), n1 = ld(t0 + 5), n2 = ld(t0 + 6), n3 = ld(t0 + 7);
#pragma unroll
        for (int k = 0; k < 4; k++) {
            int t = t0 + k;
            if (t >= N_STEPS) break;                      // uniform across CTA
            float inpv = (k == 0) ? a0 : (k == 1) ? a1 : (k == 2) ? a2 : a3;

            // v1 = ALPHA*v + inp - z*THR (+ recurrent from previous spikes)
            float vn = fmaf(ALPHA, v, inpv) - zf * THR;
            if (any_prev) {
#pragma unroll 4
                for (int w = 0; w < 16; w++) {
                    unsigned m = smask[p][w];
                    int sb = w * 32;
                    while (m) {
                        int s = sb + __ffs((int)m) - 1;
                        m &= (m - 1);
                        vn += g_wrecT[((size_t)s << 9) + tid];  // diag already 0
                    }
                }
            }
            int z = vn > THR;
            v  = vn;
            zf = z ? 1.0f : 0.0f;

            unsigned bal = __ballot_sync(0xffffffffu, z);
            if (lane == 0) smask[p ^ 1][wid] = bal;
            int any = __syncthreads_or(z);

            if (wid == 0) {
                float vacc = KAPPA * vo;
                if (any) {
#pragma unroll 4
                    for (int w = 0; w < 16; w++) {
                        unsigned m = smask[p ^ 1][w];
                        int sb = w * 32;
                        while (m) {
                            int s = sb + __ffs((int)m) - 1;
                            m &= (m - 1);
                            vacc += g_woutT[((size_t)s << 5) + lane];
                        }
                    }
                }
                vo = vacc;
                out[(size_t)(t + 1) * (N_B * OUT_DIM) + b * OUT_DIM + lane] = vo;
            }
            any_prev = any;
            p ^= 1;
        }
        a0 = n0; a1 = n1; a2 = n2; a3 = n3;
    }
}

// ---------------------------------------------------------------------------
// Launch: masks + transposes (independent), then sparse GEMM, then scan.
// All on the capture stream, no sync, no allocation.
// ---------------------------------------------------------------------------
extern "C" void kernel_launch(void* const* d_in, const int* in_sizes, int n_in,
                              void* d_out, int out_size) {
    const float* x     = (const float*)d_in[0];
    const float* w_inp = (const float*)d_in[1];
    const float* w_rec = (const float*)d_in[2];
    const float* w_out = (const float*)d_in[3];
    // d_in[4] = tp (unused scalar)
    float* out = (float*)d_out;

    cudaFuncSetAttribute(k_inp_kernel,
                         cudaFuncAttributeMaxDynamicSharedMemorySize, K_INP_SMEM);

    k_masks<<<dim3(N_B, 4), 256>>>(x);
    k_prep<<<256, 256>>>(w_rec, w_out, w_inp);
    k_inp_kernel<<<dim3(4, 148), 256, K_INP_SMEM>>>();
    k_scan<<<N_B, 512>>>(out);
}

// round 2
// speedup vs baseline: 2.7264x; 2.7264x over previous
#include <cuda_runtime.h>
#include <cstdint>

// ---------------------------------------------------------------------------
// SRNN forward:
//   inp_cur[t,b,r] = sum_i x[b,i,t] * w_inp[r,i]
//   per step t=0..998:
//     v1  = ALPHA*v + z @ w_rec_eff.T + inp_cur[t] - z*THR   (w_rec diag zeroed)
//     z1  = (v1 > THR); vo1 = KAPPA*vo + z1 @ w_out.T
//   out[0]=0, out[t+1]=vo1.  out shape (1000,128,32) f32
// ---------------------------------------------------------------------------

#define N_B      128
#define INP_DIM  256
#define N_T      1000
#define N_REC    512
#define OUT_DIM  32
#define N_STEPS  999

#define ALPHA 0.9512294245007140f
#define KAPPA 0.9512294245007140f
#define THR   0.6f

#define ROWS  (N_STEPS * N_B)      // 127872 = 864 * 148
#define ROWS_PER_CTA 864

// ---- scratch (__device__ globals; no allocation) ----
__device__ float    g_inp[(size_t)N_B * N_STEPS * N_REC];   // (b,t,r), 262 MB
__device__ unsigned g_masks[(size_t)ROWS * 8];              // 256-bit mask per (t,b)
__device__ float    g_wrecT[N_REC * N_REC];                 // [s][r], diag 0
__device__ float    g_woutT[N_REC * OUT_DIM];               // [r][o]
__device__ float    g_winpT[INP_DIM * N_REC];               // [i][r]

// ---------------------------------------------------------------------------
// Kernel 1: pack x (b,i,t) into per-(t,b) 256-bit masks. Coalesced over t.
// ---------------------------------------------------------------------------
__global__ void k_masks(const float* __restrict__ x) {
    int b = blockIdx.x;
    int t = blockIdx.y * 256 + threadIdx.x;
    if (t >= N_STEPS) return;

    unsigned m[8] = {0,0,0,0,0,0,0,0};
    const float* xp = x + (size_t)b * INP_DIM * N_T + t;
#pragma unroll
    for (int i = 0; i < INP_DIM; i++) {
        if (xp[(size_t)i * N_T] > 0.5f) m[i >> 5] |= (1u << (i & 31));
    }
    unsigned* dst = g_masks + ((size_t)t * N_B + b) * 8;
#pragma unroll
    for (int w = 0; w < 8; w++) dst[w] = m[w];
}

// ---------------------------------------------------------------------------
// Kernel 2: weight transposes.
// ---------------------------------------------------------------------------
__global__ void k_prep(const float* __restrict__ w_rec,
                       const float* __restrict__ w_out,
                       const float* __restrict__ w_inp) {
    int stride = gridDim.x * blockDim.x;
    int idx0 = blockIdx.x * blockDim.x + threadIdx.x;

    for (int i = idx0; i < N_REC * N_REC; i += stride) {
        int s = i >> 9, r = i & (N_REC - 1);
        float v = w_rec[(size_t)r * N_REC + s];
        g_wrecT[i] = (r == s) ? 0.0f : v;
    }
    for (int i = idx0; i < N_REC * OUT_DIM; i += stride) {
        int r = i >> 5, o = i & 31;
        g_woutT[i] = w_out[(size_t)o * N_REC + r];
    }
    for (int i = idx0; i < INP_DIM * N_REC; i += stride) {
        int ii = i >> 9, r = i & (N_REC - 1);
        g_winpT[i] = w_inp[(size_t)r * INP_DIM + ii];
    }
}

// ---------------------------------------------------------------------------
// Kernel 3: sparse input GEMM — warp-per-row, no barriers.
//   grid (4 rec-slices, 148 chunks), 256 threads (8 warps).
//   Smem: w_inpT slice [256 i][128 r] fp32 (128 KB).
//   Per row: one 32B coalesced mask load, ~26 active bits, each an LDS.128.
// ---------------------------------------------------------------------------
#define K_INP_SMEM (INP_DIM * 128 * 4)

__global__ void __launch_bounds__(256) k_inp_kernel() {
    extern __shared__ float w_sh[];               // [256][128]

    int slice = blockIdx.x;                       // 0..3
    int chunk = blockIdx.y;                       // 0..147
    int tid   = threadIdx.x;
    int wid   = tid >> 5;
    int lane  = tid & 31;
    int r0    = slice * 128;

    for (int idx = tid; idx < INP_DIM * 128; idx += 256) {
        int i = idx >> 7, rr = idx & 127;
        w_sh[idx] = g_winpT[(size_t)i * N_REC + r0 + rr];
    }
    __syncthreads();

    int rowbase = chunk * ROWS_PER_CTA;
    // warp processes rows rowbase + wid + 8*j, j = 0..107, mask prefetched 1 ahead
    int row0 = rowbase + wid;
    unsigned mw = (lane < 8) ? __ldg(&g_masks[(size_t)row0 * 8 + lane]) : 0u;

    for (int j = 0; j < ROWS_PER_CTA / 8; j++) {
        int row = rowbase + j * 8 + wid;
        unsigned curw = mw;
        if (j < ROWS_PER_CTA / 8 - 1)
            mw = (lane < 8) ? __ldg(&g_masks[(size_t)(row + 8) * 8 + lane]) : 0u;

        float4 acc = make_float4(0.f, 0.f, 0.f, 0.f);
#pragma unroll
        for (int w = 0; w < 8; w++) {
            unsigned m = __shfl_sync(0xffffffffu, curw, w);
            int ibase = w * 32;
            while (m) {
                int i = ibase + __ffs((int)m) - 1;
                m &= (m - 1);
                float4 wv = *(const float4*)&w_sh[(i << 7) + (lane << 2)];
                acc.x += wv.x; acc.y += wv.y; acc.z += wv.z; acc.w += wv.w;
            }
        }
        int t = row >> 7, bb = row & 127;         // row = t*128 + b
        float4* dst = (float4*)(g_inp + ((size_t)bb * N_STEPS + t) * N_REC + r0) + lane;
        *dst = acc;
    }
}

// ---------------------------------------------------------------------------
// Kernel 4: sequential scan. 1 CTA per batch, 128 threads, 4 neurons/thread.
//   float4 input loads, 8-step register prefetch, 4 ballots/warp per step,
//   one __syncthreads_or per step. Warp 0 owns the 32 outputs.
// ---------------------------------------------------------------------------
__global__ void __launch_bounds__(128) k_scan(float* __restrict__ out) {
    __shared__ unsigned smask[2][16];   // [buf][wid*4+j], bit lane -> neuron wid*128+lane*4+j

    int b    = blockIdx.x;
    int tid  = threadIdx.x;
    int wid  = tid >> 5;
    int lane = tid & 31;

    float4 v  = make_float4(0.f, 0.f, 0.f, 0.f);
    float4 zf = make_float4(0.f, 0.f, 0.f, 0.f);
    float  vo = 0.f;
    int any_prev = 0, p = 0;

    const float4* inp = (const float4*)(g_inp + (size_t)b * N_STEPS * N_REC) + tid;

    if (wid == 0) out[(size_t)b * OUT_DIM + lane] = 0.f;   // out[0] = 0

    auto ld = [&](int t) {
        int tc = t < N_STEPS ? t : (N_STEPS - 1);
        return inp[(size_t)tc * (N_REC / 4)];
    };

    float4 a[8];
#pragma unroll
    for (int k = 0; k < 8; k++) a[k] = ld(k);

    for (int t0 = 0; t0 < N_STEPS; t0 += 8) {
        float4 nb[8];
#pragma unroll
        for (int k = 0; k < 8; k++) nb[k] = ld(t0 + 8 + k);

#pragma unroll
        for (int k = 0; k < 8; k++) {
            int t = t0 + k;
            if (t >= N_STEPS) break;               // uniform across CTA
            float4 cur = a[k];

            float4 vn;
            vn.x = fmaf(ALPHA, v.x, cur.x) - zf.x * THR;
            vn.y = fmaf(ALPHA, v.y, cur.y) - zf.y * THR;
            vn.z = fmaf(ALPHA, v.z, cur.z) - zf.z * THR;
            vn.w = fmaf(ALPHA, v.w, cur.w) - zf.w * THR;

            if (any_prev) {                        // recurrent gather (rare)
#pragma unroll 4
                for (int wd = 0; wd < 16; wd++) {
                    unsigned m = smask[p][wd];
                    while (m) {
                        int l = __ffs((int)m) - 1;
                        m &= (m - 1);
                        int s = ((wd >> 2) << 7) + (l << 2) + (wd & 3);
                        const float4 wv =
                            *(const float4*)(g_wrecT + ((size_t)s << 9) + (tid << 2));
                        vn.x += wv.x; vn.y += wv.y; vn.z += wv.z; vn.w += wv.w;
                    }
                }
            }
            int z0 = vn.x > THR, z1 = vn.y > THR, z2 = vn.z > THR, z3 = vn.w > THR;
            v = vn;
            zf = make_float4(z0 ? 1.f : 0.f, z1 ? 1.f : 0.f,
                             z2 ? 1.f : 0.f, z3 ? 1.f : 0.f);

            unsigned b0 = __ballot_sync(0xffffffffu, z0);
            unsigned b1 = __ballot_sync(0xffffffffu, z1);
            unsigned b2 = __ballot_sync(0xffffffffu, z2);
            unsigned b3 = __ballot_sync(0xffffffffu, z3);
            if (lane < 4)
                smask[p ^ 1][wid * 4 + lane] =
                    (lane == 0) ? b0 : (lane == 1) ? b1 : (lane == 2) ? b2 : b3;

            int any = __syncthreads_or(z0 | z1 | z2 | z3);

            if (wid == 0) {                        // 32 outputs on warp 0
                float vacc = KAPPA * vo;
                if (any) {
#pragma unroll 4
                    for (int wd = 0; wd < 16; wd++) {
                        unsigned m = smask[p ^ 1][wd];
                        while (m) {
                            int l = __ffs((int)m) - 1;
                            m &= (m - 1);
                            int s = ((wd >> 2) << 7) + (l << 2) + (wd & 3);
                            vacc += g_woutT[(s << 5) + lane];
                        }
                    }
                }
                vo = vacc;
                out[(size_t)(t + 1) * (N_B * OUT_DIM) + b * OUT_DIM + lane] = vo;
            }
            any_prev = any;
            p ^= 1;
        }
#pragma unroll
        for (int k = 0; k < 8; k++) a[k] = nb[k];
    }
}

// ---------------------------------------------------------------------------
extern "C" void kernel_launch(void* const* d_in, const int* in_sizes, int n_in,
                              void* d_out, int out_size) {
    const float* x     = (const float*)d_in[0];
    const float* w_inp = (const float*)d_in[1];
    const float* w_rec = (const float*)d_in[2];
    const float* w_out = (const float*)d_in[3];
    float* out = (float*)d_out;

    cudaFuncSetAttribute(k_inp_kernel,
                         cudaFuncAttributeMaxDynamicSharedMemorySize, K_INP_SMEM);

    k_masks<<<dim3(N_B, 4), 256>>>(x);
    k_prep<<<256, 256>>>(w_rec, w_out, w_inp);
    k_inp_kernel<<<dim3(4, 148), 256, K_INP_SMEM>>>();
    k_scan<<<N_B, 128>>>(out);
}